// round 3
// baseline (speedup 1.0000x reference)
#include <cuda_runtime.h>

#define H 128
#define F 166
#define NMAX 100000
#define EMAX 600000

typedef unsigned int u32;
typedef unsigned long long u64;

// ---------------- scratch (static device memory; no allocs) ----------------
__device__ float g_h[(size_t)NMAX * H];
__device__ float g_r[(size_t)NMAX * H];
__device__ float g_z[(size_t)NMAX * H];
__device__ float g_hc[(size_t)NMAX * H];
__device__ float g_hlrec[(size_t)NMAX * H];
__device__ float g_hlhis[(size_t)NMAX * H];
__device__ float g_aggrec[(size_t)NMAX * H];
__device__ float g_agghis[(size_t)NMAX * H];
__device__ float g_h2[(size_t)NMAX * H];
__device__ float g_v[(size_t)NMAX * H];
__device__ float g_ao[(size_t)NMAX * H];
__device__ float g_h3[(size_t)NMAX * H];
__device__ float g_cls[(size_t)NMAX * 64];
__device__ float g_nt[NMAX];
__device__ u32 g_degrec[NMAX], g_deghis[NMAX];
__device__ float g_disrec[NMAX], g_dishis[NMAX];
__device__ unsigned char g_upd[NMAX];
__device__ u32 g_hist1[65536], g_hist2a[65536], g_hist2b[65536];
__device__ u32 g_c1[256], g_c2a[256], g_c2b[256];
__device__ u32 g_offs[NMAX], g_cursor[NMAX], g_bsum[512];
__device__ u32 g_esrc[EMAX];
__device__ float g_ecoef[EMAX];
// scalars: 0 ntmin 1 ntmax 2 bin0 3 rank0 4 bin1 5 rank1
//          6 low0 7 lrank0 8 low1 9 lrank1 10 med_bits
__device__ u32 g_scal[16];

// ---------------- helpers ----------------
__device__ __forceinline__ u64 dup2(float x) {
    u64 r; asm("mov.b64 %0, {%1, %1};" : "=l"(r) : "f"(x)); return r;
}
__device__ __forceinline__ void fma2(u64& d, u64 a, u64 b) {
    asm("fma.rn.f32x2 %0, %1, %2, %0;" : "+l"(d) : "l"(a), "l"(b));
}
__device__ __forceinline__ float2 unpk(u64 v) {
    float2 f; asm("mov.b64 {%0, %1}, %2;" : "=f"(f.x), "=f"(f.y) : "l"(v)); return f;
}
__device__ __forceinline__ float wsum(float v) {
    #pragma unroll
    for (int o = 16; o; o >>= 1) v += __shfl_xor_sync(0xffffffffu, v, o);
    return v;
}
__device__ __forceinline__ float sigmoidf_(float x) { return 1.0f / (1.0f + expf(-x)); }

// ---------------- init ----------------
__global__ void k_init(int N) {
    int tid = blockIdx.x * blockDim.x + threadIdx.x;
    int stride = gridDim.x * blockDim.x;
    for (int i = tid; i < N; i += stride) {
        g_nt[i] = 0.0f; g_upd[i] = 0; g_degrec[i] = 0; g_deghis[i] = 0;
    }
    for (int i = tid; i < 65536; i += stride) {
        g_hist1[i] = 0; g_hist2a[i] = 0; g_hist2b[i] = 0;
    }
    if (tid == 0) { g_scal[0] = 0x7F800000u; g_scal[1] = 0u; }
}

// ---------------- edge pass 1: scatter-max nt, upd flags, median hist lvl1 --
__global__ void k_edge1(const int* __restrict__ ei, const float* __restrict__ ts, int E) {
    int e = blockIdx.x * blockDim.x + threadIdx.x;
    if (e >= E) return;
    int r = ei[e], c = ei[E + e];
    u32 tb = __float_as_uint(ts[e]);
    atomicMax((u32*)&g_nt[c], tb);   // ts >= 0 so bit order == float order
    g_upd[r] = 1; g_upd[c] = 1;
    atomicAdd(&g_hist1[tb >> 16], 1u);
}

// ---------------- min/max over nt ----------------
__global__ void k_minmax(int N) {
    int tid = blockIdx.x * blockDim.x + threadIdx.x;
    int stride = gridDim.x * blockDim.x;
    u32 mn = 0x7F800000u, mx = 0u;
    for (int i = tid; i < N; i += stride) {
        u32 b = __float_as_uint(g_nt[i]);
        mn = min(mn, b); mx = max(mx, b);
    }
    #pragma unroll
    for (int o = 16; o; o >>= 1) {
        mn = min(mn, __shfl_xor_sync(0xffffffffu, mn, o));
        mx = max(mx, __shfl_xor_sync(0xffffffffu, mx, o));
    }
    if ((threadIdx.x & 31) == 0) {
        atomicMin(&g_scal[0], mn);
        atomicMax(&g_scal[1], mx);
    }
}

// ---------------- coarse sums for histogram select ----------------
// grid = 256 (one hist) or 512 (two hists)
__global__ void k_coarse(const u32* __restrict__ hist, u32* __restrict__ out,
                         const u32* __restrict__ hist2, u32* __restrict__ out2) {
    __shared__ u32 sh[8];
    int b = blockIdx.x, t = threadIdx.x;
    const u32* hp = hist; u32* op = out;
    if (b >= 256) { b -= 256; hp = hist2; op = out2; }
    u32 v = hp[b * 256 + t];
    #pragma unroll
    for (int o = 16; o; o >>= 1) v += __shfl_xor_sync(0xffffffffu, v, o);
    if ((t & 31) == 0) sh[t >> 5] = v;
    __syncthreads();
    if (t == 0) {
        u32 s = 0;
        #pragma unroll
        for (int i = 0; i < 8; i++) s += sh[i];
        op[b] = s;
    }
}

// ---------------- k-th select using coarse + fine scans ----------------
__global__ void k_selectf(const u32* __restrict__ hist, const u32* __restrict__ coarse,
                          u32 k_imm, int kidx, int oidx) {
    __shared__ u32 sh[256];
    __shared__ u32 s_tb, s_kb;
    int t = threadIdx.x;
    u32 k = (kidx >= 0) ? g_scal[kidx] : k_imm;
    u32 v = coarse[t];
    u32 x = v;
    sh[t] = x; __syncthreads();
    for (int off = 1; off < 256; off <<= 1) {
        u32 a = (t >= off) ? sh[t - off] : 0u;
        __syncthreads();
        x += a; sh[t] = x;
        __syncthreads();
    }
    if (k < x && k >= x - v) { s_tb = (u32)t; s_kb = x - v; }
    __syncthreads();
    u32 tb = s_tb, kb = s_kb;
    u32 v2 = hist[tb * 256 + t];
    u32 x2 = v2;
    sh[t] = x2; __syncthreads();
    for (int off = 1; off < 256; off <<= 1) {
        u32 a = (t >= off) ? sh[t - off] : 0u;
        __syncthreads();
        x2 += a; sh[t] = x2;
        __syncthreads();
    }
    u32 k2 = k - kb;
    if (k2 < x2 && k2 >= x2 - v2) {
        g_scal[oidx] = tb * 256 + (u32)t;
        g_scal[oidx + 1] = k2 - (x2 - v2);
    }
}

// ---------------- median hist level 2 ----------------
__global__ void k_hist2(const float* __restrict__ ts, int E) {
    int e = blockIdx.x * blockDim.x + threadIdx.x;
    if (e >= E) return;
    u32 tb = __float_as_uint(ts[e]);
    u32 hi = tb >> 16;
    if (hi == g_scal[2]) atomicAdd(&g_hist2a[tb & 0xFFFFu], 1u);
    if (hi == g_scal[4]) atomicAdd(&g_hist2b[tb & 0xFFFFu], 1u);
}

__global__ void k_med() {
    float v0 = __uint_as_float((g_scal[2] << 16) | g_scal[6]);
    float v1 = __uint_as_float((g_scal[4] << 16) | g_scal[8]);
    g_scal[10] = __float_as_uint(0.5f * (v0 + v1));
}

// ---------------- per-path in-degree ----------------
__global__ void k_deg(const int* __restrict__ ei, const float* __restrict__ ts, int E) {
    int e = blockIdx.x * blockDim.x + threadIdx.x;
    if (e >= E) return;
    float med = __uint_as_float(g_scal[10]);
    int c = ei[E + e];
    if (ts[e] >= med) atomicAdd(&g_degrec[c], 1u);
    else atomicAdd(&g_deghis[c], 1u);
}

// ---------------- CSR build ----------------
__global__ void k_scan1(int N) {
    __shared__ u32 sh[1024];
    int t = threadIdx.x;
    int i = blockIdx.x * 1024 + t;
    u32 v = (i < N) ? (g_degrec[i] + g_deghis[i]) : 0u;
    sh[t] = v;
    __syncthreads();
    for (int off = 1; off < 1024; off <<= 1) {
        u32 a = (t >= off) ? sh[t - off] : 0u;
        __syncthreads();
        sh[t] += a;
        __syncthreads();
    }
    if (i < N) g_offs[i] = sh[t];             // inclusive within block
    if (t == 1023) g_bsum[blockIdx.x] = sh[1023];
}

__global__ void k_scan2(int NB) {
    if (threadIdx.x == 0) {
        u32 run = 0;
        for (int b = 0; b < NB; b++) { u32 t2 = g_bsum[b]; g_bsum[b] = run; run += t2; }
    }
}

__global__ void k_scan3(int N) {
    int i = blockIdx.x * blockDim.x + threadIdx.x;
    if (i >= N) return;
    u32 cr = g_degrec[i], ch = g_deghis[i];
    u32 excl = g_offs[i] - (cr + ch) + g_bsum[i >> 10];
    g_offs[i] = excl;
    g_cursor[i] = excl;
    g_disrec[i] = rsqrtf((float)cr + 1.0f);
    g_dishis[i] = rsqrtf((float)ch + 1.0f);
}

__global__ void k_fill(const int* __restrict__ ei, const float* __restrict__ ts, int E) {
    int e = blockIdx.x * blockDim.x + threadIdx.x;
    if (e >= E) return;
    float med = __uint_as_float(g_scal[10]);
    int r = ei[e], c = ei[E + e];
    bool rec = ts[e] >= med;
    float coef = rec ? (g_disrec[r] * g_disrec[c]) : (g_dishis[r] * g_dishis[c]);
    u32 p = atomicAdd(&g_cursor[c], 1u);
    g_esrc[p] = ((u32)r << 1) | (rec ? 1u : 0u);
    g_ecoef[p] = coef;
}

// ---------------- fused GEMM: C = epi(A@W^T [+ A2@W2^T]) ----------------
struct Epi {
    const float* bias;
    const float* bias2;
    const float* wtime;
    const float* ex1;
    const float* ex2;
    const float* ex3;
    const float* mem;
    const unsigned char* upd;
    const float* nt;
};

#define ASTR 80   // 64 rows + 16 pad floats (2-way store conflicts)

template <int K, int NOUT, int MODE, bool DUAL>
__global__ void __launch_bounds__(256, 2)
k_gemm(const float* __restrict__ A, const float* __restrict__ W,
       const float* __restrict__ A2, const float* __restrict__ W2,
       int N, Epi ep, float* __restrict__ C) {
    extern __shared__ float sm[];
    float* As = sm;                       // [K][ASTR]
    constexpr int WST = NOUT + 8;
    float* Ws = sm + (size_t)K * ASTR;    // [K][WST]
    const int tx = threadIdx.x;
    const int lane = tx & 31, wp = tx >> 5;
    const int row0 = blockIdx.x * 64;
    constexpr int CPT = NOUT / 32;
    u64 acc[4][CPT];
    #pragma unroll
    for (int p = 0; p < 4; p++)
        #pragma unroll
        for (int n = 0; n < CPT; n++) acc[p][n] = 0ull;

    #pragma unroll
    for (int pass = 0; pass < (DUAL ? 2 : 1); pass++) {
        const float* Ap = pass ? A2 : A;
        const float* Wp = pass ? W2 : W;
        if (pass) __syncthreads();
        #pragma unroll 1
        for (int idx = tx; idx < 64 * K; idx += 256) {
            int r = idx / K, k = idx - r * K;   // K compile-time: mul-shift
            float v = (row0 + r < N) ? Ap[(size_t)(row0 + r) * K + k] : 0.0f;
            As[k * ASTR + r] = v;
        }
        #pragma unroll 1
        for (int idx = tx; idx < NOUT * K; idx += 256) {
            int j = idx / K, k = idx - j * K;
            Ws[k * WST + j] = Wp[idx];
        }
        __syncthreads();
        #pragma unroll 4
        for (int kk = 0; kk < K; kk++) {
            ulonglong2 a01 = *(const ulonglong2*)&As[kk * ASTR + wp * 8];
            ulonglong2 a23 = *(const ulonglong2*)&As[kk * ASTR + wp * 8 + 4];
            u64 ap[4] = {a01.x, a01.y, a23.x, a23.y};
            float bw[CPT];
            if (CPT == 4) {
                float4 b4 = *(const float4*)&Ws[kk * WST + lane * 4];
                bw[0] = b4.x; bw[1] = b4.y; bw[2] = b4.z; bw[3] = b4.w;
            } else {
                float2 b2 = *(const float2*)&Ws[kk * WST + lane * 2];
                bw[0] = b2.x; bw[1] = b2.y;
            }
            #pragma unroll
            for (int n = 0; n < CPT; n++) {
                u64 bd = dup2(bw[n]);
                #pragma unroll
                for (int p = 0; p < 4; p++) fma2(acc[p][n], ap[p], bd);
            }
        }
    }

    // epilogue: vectorized stores
    #pragma unroll
    for (int p = 0; p < 4; p++) {
        #pragma unroll
        for (int half = 0; half < 2; half++) {
            int i = row0 + wp * 8 + 2 * p + half;
            if (i >= N) continue;
            float vv[CPT];
            #pragma unroll
            for (int n = 0; n < CPT; n++) {
                float2 f = unpk(acc[p][n]);
                vv[n] = half ? f.y : f.x;
            }
            const int c0 = lane * CPT;
            if (MODE == 1) {
                #pragma unroll
                for (int n = 0; n < CPT; n++) vv[n] += ep.bias[c0 + n];
            } else if (MODE == 2) {
                #pragma unroll
                for (int n = 0; n < CPT; n++) vv[n] = fmaxf(vv[n] + ep.bias[c0 + n], 0.0f);
            } else if (MODE == 3) {
                #pragma unroll
                for (int n = 0; n < CPT; n++)
                    vv[n] = sigmoidf_(vv[n] + ep.bias[c0 + n] + ep.bias2[c0 + n]);
            } else if (MODE == 4) {
                float ntv = ep.nt[i];
                float tmin = __uint_as_float(g_scal[0]);
                float tmax = __uint_as_float(g_scal[1]);
                float ntn = (tmax > tmin) ? (ntv - tmin) / (tmax - tmin + 1e-8f) : ntv;
                float4 mv = *(const float4*)&ep.mem[(size_t)i * H + c0];
                float mvv[4] = {mv.x, mv.y, mv.z, mv.w};
                #pragma unroll
                for (int n = 0; n < CPT; n++)
                    vv[n] = fmaxf(vv[n] + ep.bias[c0 + n] + ntn * ep.wtime[c0 + n] + ep.bias2[c0 + n], 0.0f)
                            + mvv[n];
            } else if (MODE == 5) {
                float4 hc4 = *(const float4*)&ep.ex1[(size_t)i * NOUT + c0];
                float4 r4 = *(const float4*)&ep.ex2[(size_t)i * NOUT + c0];
                float4 z4 = *(const float4*)&ep.ex3[(size_t)i * NOUT + c0];
                float4 m4 = *(const float4*)&ep.mem[(size_t)i * NOUT + c0];
                float hcv[4] = {hc4.x, hc4.y, hc4.z, hc4.w};
                float rv[4] = {r4.x, r4.y, r4.z, r4.w};
                float zv[4] = {z4.x, z4.y, z4.z, z4.w};
                float mvv[4] = {m4.x, m4.y, m4.z, m4.w};
                bool u = ep.upd[i] != 0;
                #pragma unroll
                for (int n = 0; n < CPT; n++) {
                    float cc = tanhf(vv[n] + ep.bias[c0 + n] + rv[n] * hcv[n]);
                    vv[n] = u ? ((1.0f - zv[n]) * cc + zv[n] * mvv[n]) : mvv[n];
                }
            } else if (MODE == 6) {
                float4 e4 = *(const float4*)&ep.ex1[(size_t)i * NOUT + c0];
                float ev[4] = {e4.x, e4.y, e4.z, e4.w};
                #pragma unroll
                for (int n = 0; n < CPT; n++) vv[n] += ep.bias[c0 + n] + ev[n];
            }
            if (CPT == 4) {
                float4 o = make_float4(vv[0], vv[1], vv[2], vv[3]);
                *(float4*)&C[(size_t)i * NOUT + c0] = o;
            } else {
                float2 o = make_float2(vv[0], vv[1]);
                *(float2*)&C[(size_t)i * NOUT + c0] = o;
            }
        }
    }
}

// ---------------- GCN gather (warp per node, both paths at once) -----------
__global__ void k_gather(int N, const float* __restrict__ b_gr, const float* __restrict__ b_gh) {
    int gw = (blockIdx.x * blockDim.x + threadIdx.x) >> 5;
    int lane = threadIdx.x & 31;
    if (gw >= N) return;
    int i = gw;
    u32 start = g_offs[i];
    u32 cnt = g_degrec[i] + g_deghis[i];
    float4 ar = make_float4(0, 0, 0, 0), ah = make_float4(0, 0, 0, 0);
    for (u32 k = start; k < start + cnt; k++) {
        u32 pk = g_esrc[k];
        float cf = g_ecoef[k];
        int s = (int)(pk >> 1);
        if (pk & 1u) {
            float4 v = *(const float4*)&g_hlrec[(size_t)s * H + lane * 4];
            ar.x += v.x * cf; ar.y += v.y * cf; ar.z += v.z * cf; ar.w += v.w * cf;
        } else {
            float4 v = *(const float4*)&g_hlhis[(size_t)s * H + lane * 4];
            ah.x += v.x * cf; ah.y += v.y * cf; ah.z += v.z * cf; ah.w += v.w * cf;
        }
    }
    float fr = g_disrec[i] * g_disrec[i];
    float fh = g_dishis[i] * g_dishis[i];
    float4 sr = *(const float4*)&g_hlrec[(size_t)i * H + lane * 4];
    float4 sh = *(const float4*)&g_hlhis[(size_t)i * H + lane * 4];
    float4 br = *(const float4*)&b_gr[lane * 4];
    float4 bh = *(const float4*)&b_gh[lane * 4];
    float4 outr, outh;
    outr.x = ar.x + sr.x * fr + br.x; outr.y = ar.y + sr.y * fr + br.y;
    outr.z = ar.z + sr.z * fr + br.z; outr.w = ar.w + sr.w * fr + br.w;
    outh.x = ah.x + sh.x * fh + bh.x; outh.y = ah.y + sh.y * fh + bh.y;
    outh.z = ah.z + sh.z * fh + bh.z; outh.w = ah.w + sh.w * fh + bh.w;
    *(float4*)&g_aggrec[(size_t)i * H + lane * 4] = outr;
    *(float4*)&g_agghis[(size_t)i * H + lane * 4] = outh;
}

// ---------------- path softmax mix + LayerNorm (warp per node) -------------
__global__ void k_pathagg(int N, const float* __restrict__ lng, const float* __restrict__ lnb) {
    int gw = (blockIdx.x * blockDim.x + threadIdx.x) >> 5;
    int lane = threadIdx.x & 31;
    if (gw >= N) return;
    int i = gw;
    float4 hr = *(const float4*)&g_aggrec[(size_t)i * H + lane * 4];
    float4 hh = *(const float4*)&g_agghis[(size_t)i * H + lane * 4];
    float s0 = wsum(hr.x + hr.y + hr.z + hr.w) * (1.0f / H);
    float s1 = wsum(hh.x + hh.y + hh.z + hh.w) * (1.0f / H);
    float m = fmaxf(s0, s1);
    float e0 = expf(s0 - m), e1 = expf(s1 - m);
    float w0 = e0 / (e0 + e1), w1 = e1 / (e0 + e1);
    float4 t;
    t.x = hr.x * w0 + hh.x * w1; t.y = hr.y * w0 + hh.y * w1;
    t.z = hr.z * w0 + hh.z * w1; t.w = hr.w * w0 + hh.w * w1;
    float mean = wsum(t.x + t.y + t.z + t.w) * (1.0f / H);
    float4 d;
    d.x = t.x - mean; d.y = t.y - mean; d.z = t.z - mean; d.w = t.w - mean;
    float var = wsum(d.x * d.x + d.y * d.y + d.z * d.z + d.w * d.w) * (1.0f / H);
    float inv = rsqrtf(var + 1e-5f);
    float4 gv = *(const float4*)&lng[lane * 4];
    float4 bv = *(const float4*)&lnb[lane * 4];
    float4 o;
    o.x = d.x * inv * gv.x + bv.x; o.y = d.y * inv * gv.y + bv.y;
    o.z = d.z * inv * gv.z + bv.z; o.w = d.w * inv * gv.w + bv.w;
    *(float4*)&g_h2[(size_t)i * H + lane * 4] = o;
}

// ---------------- plain LayerNorm over g_ao -> g_h3 ----------------
__global__ void k_ln(int N, const float* __restrict__ lng, const float* __restrict__ lnb) {
    int gw = (blockIdx.x * blockDim.x + threadIdx.x) >> 5;
    int lane = threadIdx.x & 31;
    if (gw >= N) return;
    int i = gw;
    float4 t = *(const float4*)&g_ao[(size_t)i * H + lane * 4];
    float mean = wsum(t.x + t.y + t.z + t.w) * (1.0f / H);
    float4 d;
    d.x = t.x - mean; d.y = t.y - mean; d.z = t.z - mean; d.w = t.w - mean;
    float var = wsum(d.x * d.x + d.y * d.y + d.z * d.z + d.w * d.w) * (1.0f / H);
    float inv = rsqrtf(var + 1e-5f);
    float4 gv = *(const float4*)&lng[lane * 4];
    float4 bv = *(const float4*)&lnb[lane * 4];
    float4 o;
    o.x = d.x * inv * gv.x + bv.x; o.y = d.y * inv * gv.y + bv.y;
    o.z = d.z * inv * gv.z + bv.z; o.w = d.w * inv * gv.w + bv.w;
    *(float4*)&g_h3[(size_t)i * H + lane * 4] = o;
}

// ---------------- final tiny classifier layer (warp per node) --------------
__global__ void k_logits(int N, const float* __restrict__ W2, const float* __restrict__ b2,
                         float* __restrict__ out) {
    int gw = (blockIdx.x * blockDim.x + threadIdx.x) >> 5;
    int lane = threadIdx.x & 31;
    if (gw >= N) return;
    int i = gw;
    float v0 = g_cls[(size_t)i * 64 + lane];
    float v1 = g_cls[(size_t)i * 64 + 32 + lane];
    float d0 = v0 * W2[lane] + v1 * W2[32 + lane];
    float d1 = v0 * W2[64 + lane] + v1 * W2[96 + lane];
    d0 = wsum(d0);
    d1 = wsum(d1);
    if (lane == 0) {
        out[(size_t)i * 2 + 0] = d0 + b2[0];
        out[(size_t)i * 2 + 1] = d1 + b2[1];
    }
}

// ---------------- host launcher ----------------
template <int K, int NOUT, int MODE, bool DUAL>
static void gemm_launch(const float* A, const float* W, const float* A2, const float* W2,
                        int N, const Epi& ep, float* C) {
    size_t smem = (size_t)K * ASTR * sizeof(float) + (size_t)K * (NOUT + 8) * sizeof(float);
    cudaFuncSetAttribute(k_gemm<K, NOUT, MODE, DUAL>,
                         cudaFuncAttributeMaxDynamicSharedMemorySize, (int)smem);
    k_gemm<K, NOUT, MODE, DUAL><<<(N + 63) / 64, 256, smem>>>(A, W, A2, W2, N, ep, C);
}

extern "C" void kernel_launch(void* const* d_in, const int* in_sizes, int n_in,
                              void* d_out, int out_size) {
    const float* x       = (const float*)d_in[0];
    const int*   ei      = (const int*)d_in[1];
    const float* ts      = (const float*)d_in[2];
    const float* mem     = (const float*)d_in[3];
    const float* W_in    = (const float*)d_in[4];
    const float* b_in    = (const float*)d_in[5];
    const float* W_time  = (const float*)d_in[6];
    const float* b_time  = (const float*)d_in[7];
    const float* W_ih    = (const float*)d_in[8];
    const float* W_hh    = (const float*)d_in[9];
    const float* b_ih    = (const float*)d_in[10];
    const float* b_hh    = (const float*)d_in[11];
    const float* W_gr    = (const float*)d_in[12];
    const float* b_gr    = (const float*)d_in[13];
    const float* W_gh    = (const float*)d_in[14];
    const float* b_gh    = (const float*)d_in[15];
    const float* ln_pa_g = (const float*)d_in[16];
    const float* ln_pa_b = (const float*)d_in[17];
    const float* Wv      = (const float*)d_in[18];
    const float* bv      = (const float*)d_in[19];
    const float* Wo      = (const float*)d_in[20];
    const float* bo      = (const float*)d_in[21];
    const float* ln_at_g = (const float*)d_in[22];
    const float* ln_at_b = (const float*)d_in[23];
    const float* W1      = (const float*)d_in[24];
    const float* b1      = (const float*)d_in[25];
    const float* W2p     = (const float*)d_in[26];
    const float* b2      = (const float*)d_in[27];

    const int E = in_sizes[2];
    const int N = in_sizes[0] / F;
    float* out_logits = (float*)d_out;
    float* out_mem = (float*)d_out + (size_t)2 * N;

    float *p_h, *p_r, *p_z, *p_hc, *p_hlrec, *p_hlhis, *p_h2, *p_v, *p_ao, *p_h3, *p_cls, *p_nt;
    unsigned char* p_upd;
    u32 *p_h1, *p_h2a, *p_h2b, *p_c1, *p_c2a, *p_c2b;
    cudaGetSymbolAddress((void**)&p_h, g_h);
    cudaGetSymbolAddress((void**)&p_r, g_r);
    cudaGetSymbolAddress((void**)&p_z, g_z);
    cudaGetSymbolAddress((void**)&p_hc, g_hc);
    cudaGetSymbolAddress((void**)&p_hlrec, g_hlrec);
    cudaGetSymbolAddress((void**)&p_hlhis, g_hlhis);
    cudaGetSymbolAddress((void**)&p_h2, g_h2);
    cudaGetSymbolAddress((void**)&p_v, g_v);
    cudaGetSymbolAddress((void**)&p_ao, g_ao);
    cudaGetSymbolAddress((void**)&p_h3, g_h3);
    cudaGetSymbolAddress((void**)&p_cls, g_cls);
    cudaGetSymbolAddress((void**)&p_nt, g_nt);
    cudaGetSymbolAddress((void**)&p_upd, g_upd);
    cudaGetSymbolAddress((void**)&p_h1, g_hist1);
    cudaGetSymbolAddress((void**)&p_h2a, g_hist2a);
    cudaGetSymbolAddress((void**)&p_h2b, g_hist2b);
    cudaGetSymbolAddress((void**)&p_c1, g_c1);
    cudaGetSymbolAddress((void**)&p_c2a, g_c2a);
    cudaGetSymbolAddress((void**)&p_c2b, g_c2b);

    const u32 k0 = (u32)((E - 1) / 2);
    const u32 k1 = (u32)(E / 2);
    const int EB = (E + 255) / 256;
    const int NB1024 = (N + 1023) / 1024;
    const int NWB = (N * 32 + 255) / 256;   // warp-per-node grids

    // ---- preprocessing (ordered so launch #6 = an H x H GEMM for ncu) ----
    k_init<<<256, 256>>>(N);                                       // 1
    k_edge1<<<EB, 256>>>(ei, ts, E);                               // 2
    k_minmax<<<256, 256>>>(N);                                     // 3
    k_coarse<<<256, 256>>>(p_h1, p_c1, p_h1, p_c1);                // 4
    k_selectf<<<1, 256>>>(p_h1, p_c1, k0, -1, 2);                  // 5
    // hc = mem @ W_hh[2H:3H]^T + b_hh[2H:]  (independent of preprocessing)
    {
        Epi ep{}; ep.bias = b_hh + 2 * H;                          // 6 <- profiled
        gemm_launch<H, H, 1, false>(mem, W_hh + 2 * H * H, nullptr, nullptr, N, ep, p_hc);
    }
    k_selectf<<<1, 256>>>(p_h1, p_c1, k1, -1, 4);
    k_hist2<<<EB, 256>>>(ts, E);
    k_coarse<<<512, 256>>>(p_h2a, p_c2a, p_h2b, p_c2b);
    k_selectf<<<1, 256>>>(p_h2a, p_c2a, 0, 3, 6);
    k_selectf<<<1, 256>>>(p_h2b, p_c2b, 0, 5, 8);
    k_med<<<1, 1>>>();
    k_deg<<<EB, 256>>>(ei, ts, E);
    k_scan1<<<NB1024, 1024>>>(N);
    k_scan2<<<1, 1>>>(NB1024);
    k_scan3<<<(N + 255) / 256, 256>>>(N);
    k_fill<<<EB, 256>>>(ei, ts, E);

    // ---- h = relu(x@W_in^T + b_in + nt*W_time + b_time) + memory ----
    {
        Epi ep{}; ep.bias = b_in; ep.bias2 = b_time; ep.wtime = W_time; ep.mem = mem; ep.nt = p_nt;
        gemm_launch<F, H, 4, false>(x, W_in, nullptr, nullptr, N, ep, p_h);
    }
    // ---- GRU gates ----
    {
        Epi ep{}; ep.bias = b_ih; ep.bias2 = b_hh;
        gemm_launch<H, H, 3, true>(p_h, W_ih, mem, W_hh, N, ep, p_r);
    }
    {
        Epi ep{}; ep.bias = b_ih + H; ep.bias2 = b_hh + H;
        gemm_launch<H, H, 3, true>(p_h, W_ih + H * H, mem, W_hh + H * H, N, ep, p_z);
    }
    {
        Epi ep{}; ep.bias = b_ih + 2 * H; ep.ex1 = p_hc; ep.ex2 = p_r; ep.ex3 = p_z;
        ep.mem = mem; ep.upd = p_upd;
        gemm_launch<H, H, 5, false>(p_h, W_ih + 2 * H * H, nullptr, nullptr, N, ep, out_mem);
    }
    // ---- GCN linears + gather + path aggregation ----
    {
        Epi ep{};
        gemm_launch<H, H, 0, false>(p_h, W_gr, nullptr, nullptr, N, ep, p_hlrec);
        gemm_launch<H, H, 0, false>(p_h, W_gh, nullptr, nullptr, N, ep, p_hlhis);
    }
    k_gather<<<NWB, 256>>>(N, b_gr, b_gh);
    k_pathagg<<<NWB, 256>>>(N, ln_pa_g, ln_pa_b);
    // ---- attention (degenerate) + LN ----
    {
        Epi ep{}; ep.bias = bv;
        gemm_launch<H, H, 1, false>(p_h2, Wv, nullptr, nullptr, N, ep, p_v);
    }
    {
        Epi ep{}; ep.bias = bo; ep.ex1 = p_h2;
        gemm_launch<H, H, 6, false>(p_v, Wo, nullptr, nullptr, N, ep, p_ao);
    }
    k_ln<<<NWB, 256>>>(N, ln_at_g, ln_at_b);
    // ---- classifier ----
    {
        Epi ep{}; ep.bias = b1;
        gemm_launch<H, 64, 2, false>(p_h3, W1, nullptr, nullptr, N, ep, p_cls);
    }
    k_logits<<<NWB, 256>>>(N, W2p, b2, out_logits);
}